// round 2
// baseline (speedup 1.0000x reference)
#include <cuda_runtime.h>

#define BB 8
#define CC 32
#define HH 384
#define WW 768
#define HW  (HH * WW)
#define CHW ((size_t)CC * HH * WW)

__global__ __launch_bounds__(768, 2)
void disparity_warp_rows(const float* __restrict__ src,
                         const float* __restrict__ disp,
                         float* __restrict__ out) {
    __shared__ float s[2][2][WW];   // [buffer][row0/row1][x]

    const int w = threadIdx.x;          // 0..767
    const int h = blockIdx.x % HH;
    const int b = blockIdx.x / HH;

    // per-pixel horizontal coords
    float d  = disp[(size_t)b * HW + (size_t)h * WW + w];
    float ix = ((float)w - d) * (768.0f / 767.0f) - 0.5f;
    float iy = (float)h * (384.0f / 383.0f) - 0.5f;

    float x0f = floorf(ix);
    float y0f = floorf(iy);
    float fx = ix - x0f;
    float fy = iy - y0f;
    int x0 = (int)x0f, x1 = x0 + 1;
    int y0 = (int)y0f, y1 = y0 + 1;

    // zero-padding masks folded into weights
    bool xi0 = (x0 >= 0) & (x0 < WW);
    bool xi1 = (x1 >= 0) & (x1 < WW);
    bool yi0 = (y0 >= 0) & (y0 < HH);
    bool yi1 = (y1 >= 0) & (y1 < HH);

    float w00 = (1.0f - fy) * (1.0f - fx) * (float)(xi0 & yi0);
    float w01 = (1.0f - fy) * fx          * (float)(xi1 & yi0);
    float w10 = fy * (1.0f - fx)          * (float)(xi0 & yi1);
    float w11 = fy * fx                   * (float)(xi1 & yi1);

    int cx0 = min(max(x0, 0), WW - 1);
    int cx1 = min(max(x1, 0), WW - 1);
    int cy0 = min(max(y0, 0), HH - 1);
    int cy1 = min(max(y1, 0), HH - 1);

    const float* sb  = src + (size_t)b * CHW;
    const float* r0p = sb + (size_t)cy0 * WW + w;   // coalesced row y0 loader
    const float* r1p = sb + (size_t)cy1 * WW + w;   // coalesced row y1 loader
    float* ob = out + (size_t)b * CHW + (size_t)h * WW + w;

    // prologue: channel 0 rows into buffer 0
    s[0][0][w] = r0p[0];
    s[0][1][w] = r1p[0];
    __syncthreads();

    #pragma unroll 4
    for (int c = 0; c < CC; ++c) {
        // prefetch next channel's rows (overlaps with LDS compute below)
        float n0 = 0.0f, n1 = 0.0f;
        if (c + 1 < CC) {
            n0 = r0p[(size_t)(c + 1) * HW];
            n1 = r1p[(size_t)(c + 1) * HW];
        }

        const float* s0 = s[c & 1][0];
        const float* s1 = s[c & 1][1];
        float v = s0[cx0] * w00 + s0[cx1] * w01
                + s1[cx0] * w10 + s1[cx1] * w11;
        ob[(size_t)c * HW] = v;

        if (c + 1 < CC) {
            s[(c + 1) & 1][0][w] = n0;
            s[(c + 1) & 1][1][w] = n1;
        }
        __syncthreads();   // single barrier per channel (double-buffered)
    }
}

extern "C" void kernel_launch(void* const* d_in, const int* in_sizes, int n_in,
                              void* d_out, int out_size) {
    const float* src  = (const float*)d_in[0];
    const float* disp = (const float*)d_in[1];
    float* out = (float*)d_out;

    disparity_warp_rows<<<BB * HH, WW>>>(src, disp, out);
}